// round 16
// baseline (speedup 1.0000x reference)
#include <cuda_runtime.h>

#define ITERS  100
#define ITERS1 12          // phase-1 cap: 4 spans of 3
#define BANK   524288      // max elements (B fixed at 524288)
#define TAILB  512         // phase-2 grid blocks

// straggler scratch (device globals: sanctioned no-alloc scratch; init 0)
__device__ int   d_cnt;
__device__ int   d_done;
__device__ int   d_idx[BANK];
__device__ float d_st[32ull * BANK];   // component-major: [comp][slot]

__device__ __forceinline__ float frcp(float x) {
    float r; asm("rcp.approx.f32 %0,%1;" : "=f"(r) : "f"(x)); return r;
}
__device__ __forceinline__ float squashf(float x) {
    float s = frcp(1.0f + __expf(-x));
    return fmaf(0.96f, s, 0.02f);
}

// ---------------- phase 1: all elements, capped at ITERS1 ----------------
__global__ void __launch_bounds__(256, 3) sk_kernel(
    const float* __restrict__ margins,
    const float* __restrict__ W1, const float* __restrict__ b1,
    const float* __restrict__ W2, const float* __restrict__ b2,
    const float* __restrict__ W3, const float* __restrict__ b3,
    const float* __restrict__ Wtau,
    float* __restrict__ out, int B)
{
    __shared__ __align__(16) float sW1[12 * 32];
    __shared__ __align__(16) float sW2[32 * 16];
    __shared__ __align__(16) float sW3[16 * 18];
    __shared__ __align__(16) float sWt[8 * 36];
    __shared__ __align__(16) float sb1[32];
    __shared__ __align__(16) float sb2[16];
    __shared__ __align__(16) float sb3[18];
    __shared__ __align__(16) float sOut[256 * 49];
    __shared__ __align__(16) float sRM[6][256];
    __shared__ __align__(16) float sCM[6][256];

    const int t = threadIdx.x;
    for (int i = t; i < 384; i += 256) sW1[i] = W1[i];
    for (int i = t; i < 512; i += 256) sW2[i] = W2[i];
    for (int i = t; i < 288; i += 256) sW3[i] = W3[i];
    for (int i = t; i < 288; i += 256) sWt[i] = Wtau[i];
    if (t < 32) sb1[t] = b1[t];
    if (t < 16) sb2[t] = b2[t];
    if (t < 18) sb3[t] = b3[t];
    __syncthreads();

    const int b = blockIdx.x * 256 + t;   // grid exactly covers B

    float m[12];
    {
        const float4* mv = (const float4*)margins + (size_t)b * 3;
        float4 q0 = mv[0], q1 = mv[1], q2 = mv[2];
        m[0] = q0.x; m[1] = q0.y; m[2]  = q0.z; m[3]  = q0.w;
        m[4] = q1.x; m[5] = q1.y; m[6]  = q1.z; m[7]  = q1.w;
        m[8] = q2.x; m[9] = q2.y; m[10] = q2.z; m[11] = q2.w;
    }

    float h[32];
#pragma unroll
    for (int j = 0; j < 32; j++) h[j] = sb1[j];
#pragma unroll
    for (int k = 0; k < 12; k++) {
        float x = m[k];
#pragma unroll
        for (int j = 0; j < 32; j++) h[j] = fmaf(x, sW1[k * 32 + j], h[j]);
    }
#pragma unroll
    for (int j = 0; j < 32; j++) h[j] = fmaxf(h[j], 0.0f);

    float g[16];
#pragma unroll
    for (int j = 0; j < 16; j++) g[j] = sb2[j];
#pragma unroll
    for (int k = 0; k < 32; k++) {
        float x = h[k];
#pragma unroll
        for (int j = 0; j < 16; j++) g[j] = fmaf(x, sW2[k * 16 + j], g[j]);
    }
#pragma unroll
    for (int j = 0; j < 16; j++) g[j] = fmaxf(g[j], 0.0f);

    float p[18];
#pragma unroll
    for (int j = 0; j < 18; j++) p[j] = sb3[j];
#pragma unroll
    for (int k = 0; k < 16; k++) {
        float x = g[k];
#pragma unroll
        for (int j = 0; j < 18; j++) p[j] = fmaf(x, sW3[k * 18 + j], p[j]);
    }

    float* so = sOut + t * 49;

    // marginals + mass balancing (proven R6)
    {
        float shm[6], shf[6];
        shm[0] = squashf(p[9]);  shm[1] = squashf(p[10]); shm[2] = 1.0f;
        shm[3] = squashf(p[11]); shm[4] = squashf(p[12]); shm[5] = 1.0f;
        shf[0] = squashf(p[13]); shf[1] = squashf(p[14]); shf[2] = 1.0f;
        shf[3] = squashf(p[15]); shf[4] = squashf(p[16]); shf[5] = 1.0f;
        float rv[6], cv[6];
        float sr = 0.f, sc = 0.f;
#pragma unroll
        for (int i = 0; i < 6; i++) {
            rv[i] = m[i] * shm[i];
            cv[i] = m[6 + i] * shf[i];
            sr += rv[i]; sc += cv[i];
            so[i * 7 + 6] = m[i]     - rv[i];
            so[42 + i]    = m[6 + i] - cv[i];
        }
        float s = __fdividef(sc, sr);
#pragma unroll
        for (int i = 0; i < 6; i++) {
            sRM[i][t] = rv[i] * s;
            sCM[i][t] = cv[i];
        }
        so[48] = 0.0f;
        out[(size_t)B * 49 + b] = __expf(p[17]);
    }

    float A[36];
#pragma unroll
    for (int e = 0; e < 36; e++) {
        float d = 0.0f;
#pragma unroll
        for (int k = 0; k < 8; k++) d = fmaf(p[k], sWt[k * 36 + e], d);
        A[e] = __expf(d);
    }

    float R[6], C[6];
#pragma unroll
    for (int i = 0; i < 6; i++) { R[i] = 1.0f; C[i] = 1.0f; }

    bool myconv = false;
#pragma unroll 1
    for (int ob = 0; ob < ITERS1 / 3; ++ob) {
        float C0o = C[0], C1o = C[1], C2o = C[2],
              C3o = C[3], C4o = C[4], C5o = C[5];
#pragma unroll
        for (int s = 0; s < 3; ++s) {
            float u0 = A[0]  * C[0];
            float u1 = A[6]  * C[0];
            float u2 = A[12] * C[0];
            float u3 = A[18] * C[0];
            float u4 = A[24] * C[0];
            float u5 = A[30] * C[0];
#pragma unroll
            for (int j = 1; j < 6; j++) {
                float cj = C[j];
                u0 = fmaf(A[j],      cj, u0);
                u1 = fmaf(A[6 + j],  cj, u1);
                u2 = fmaf(A[12 + j], cj, u2);
                u3 = fmaf(A[18 + j], cj, u3);
                u4 = fmaf(A[24 + j], cj, u4);
                u5 = fmaf(A[30 + j], cj, u5);
            }
            R[0] = sRM[0][t] * frcp(u0);
            R[1] = sRM[1][t] * frcp(u1);
            R[2] = sRM[2][t] * frcp(u2);
            R[3] = sRM[3][t] * frcp(u3);
            R[4] = sRM[4][t] * frcp(u4);
            R[5] = sRM[5][t] * frcp(u5);

            float v0 = A[0] * R[0];
            float v1 = A[1] * R[0];
            float v2 = A[2] * R[0];
            float v3 = A[3] * R[0];
            float v4 = A[4] * R[0];
            float v5 = A[5] * R[0];
#pragma unroll
            for (int i = 1; i < 6; i++) {
                float ri = R[i];
                v0 = fmaf(A[i * 6 + 0], ri, v0);
                v1 = fmaf(A[i * 6 + 1], ri, v1);
                v2 = fmaf(A[i * 6 + 2], ri, v2);
                v3 = fmaf(A[i * 6 + 3], ri, v3);
                v4 = fmaf(A[i * 6 + 4], ri, v4);
                v5 = fmaf(A[i * 6 + 5], ri, v5);
            }
            C[0] = sCM[0][t] * frcp(v0);
            C[1] = sCM[1][t] * frcp(v1);
            C[2] = sCM[2][t] * frcp(v2);
            C[3] = sCM[3][t] * frcp(v3);
            C[4] = sCM[4][t] * frcp(v4);
            C[5] = sCM[5][t] * frcp(v5);
        }
        myconv =
            fabsf(C[0] - C0o) <= 1e-5f * fabsf(C[0]) &&
            fabsf(C[1] - C1o) <= 1e-5f * fabsf(C[1]) &&
            fabsf(C[2] - C2o) <= 1e-5f * fabsf(C[2]) &&
            fabsf(C[3] - C3o) <= 1e-5f * fabsf(C[3]) &&
            fabsf(C[4] - C4o) <= 1e-5f * fabsf(C[4]) &&
            fabsf(C[5] - C5o) <= 1e-5f * fabsf(C[5]);
        if (__all_sync(__activemask(), myconv)) break;
    }

    // stragglers: append slim state (32 floats; A recomputed in phase 2)
    if (!myconv) {
        int slot = atomicAdd(&d_cnt, 1);
        d_idx[slot] = b;
#pragma unroll
        for (int k = 0; k < 8; k++)
            d_st[(size_t)k * BANK + slot] = p[k];
#pragma unroll
        for (int i = 0; i < 6; i++) {
            d_st[(size_t)(8  + i) * BANK + slot] = sRM[i][t];
            d_st[(size_t)(14 + i) * BANK + slot] = sCM[i][t];
            d_st[(size_t)(20 + i) * BANK + slot] = R[i];
            d_st[(size_t)(26 + i) * BANK + slot] = C[i];
        }
    }

    // write 6x6 block (overwritten by phase 2 for stragglers)
#pragma unroll
    for (int i = 0; i < 6; i++) {
        float Ri = R[i];
#pragma unroll
        for (int j = 0; j < 6; j++)
            so[i * 7 + j] = A[i * 6 + j] * Ri * C[j];
    }

    __syncthreads();
    {
        float4* dst = (float4*)(out + (size_t)blockIdx.x * (256 * 49));
        const float4* src = (const float4*)sOut;
#pragma unroll
        for (int idx = t, k = 0; k < 13; ++k, idx += 256) {
            if (idx < 3136) dst[idx] = src[idx];
        }
    }
}

// -------- phase 2: compacted stragglers, per-thread exit, iters 12..100 -----
__global__ void __launch_bounds__(256) sk_tail(
    const float* __restrict__ Wtau, float* __restrict__ out, int B)
{
    __shared__ __align__(16) float sWt[8 * 36];
    for (int i = threadIdx.x; i < 288; i += 256) sWt[i] = Wtau[i];
    __syncthreads();

    const int n = d_cnt;
    for (int s = blockIdx.x * 256 + threadIdx.x; s < n;
         s += gridDim.x * 256) {
        float p8[8], rm[6], cm[6], R[6], C[6];
#pragma unroll
        for (int k = 0; k < 8; k++) p8[k] = d_st[(size_t)k * BANK + s];
#pragma unroll
        for (int i = 0; i < 6; i++) {
            rm[i] = d_st[(size_t)(8  + i) * BANK + s];
            cm[i] = d_st[(size_t)(14 + i) * BANK + s];
            R[i]  = d_st[(size_t)(20 + i) * BANK + s];
            C[i]  = d_st[(size_t)(26 + i) * BANK + s];
        }

        // recompute A with identical FMA ordering as phase 1 (bit-equal)
        float A[36];
#pragma unroll
        for (int e = 0; e < 36; e++) {
            float d = 0.0f;
#pragma unroll
            for (int k = 0; k < 8; k++) d = fmaf(p8[k], sWt[k * 36 + e], d);
            A[e] = __expf(d);
        }

#pragma unroll 1
        for (int it = ITERS1; it < ITERS; it += 3) {
            float C0o = C[0], C1o = C[1], C2o = C[2],
                  C3o = C[3], C4o = C[4], C5o = C[5];
#pragma unroll
            for (int ss = 0; ss < 3; ++ss) {
                if (it + ss >= ITERS) break;
                float u0 = A[0]  * C[0];
                float u1 = A[6]  * C[0];
                float u2 = A[12] * C[0];
                float u3 = A[18] * C[0];
                float u4 = A[24] * C[0];
                float u5 = A[30] * C[0];
#pragma unroll
                for (int j = 1; j < 6; j++) {
                    float cj = C[j];
                    u0 = fmaf(A[j],      cj, u0);
                    u1 = fmaf(A[6 + j],  cj, u1);
                    u2 = fmaf(A[12 + j], cj, u2);
                    u3 = fmaf(A[18 + j], cj, u3);
                    u4 = fmaf(A[24 + j], cj, u4);
                    u5 = fmaf(A[30 + j], cj, u5);
                }
                R[0] = rm[0] * frcp(u0);
                R[1] = rm[1] * frcp(u1);
                R[2] = rm[2] * frcp(u2);
                R[3] = rm[3] * frcp(u3);
                R[4] = rm[4] * frcp(u4);
                R[5] = rm[5] * frcp(u5);

                float v0 = A[0] * R[0];
                float v1 = A[1] * R[0];
                float v2 = A[2] * R[0];
                float v3 = A[3] * R[0];
                float v4 = A[4] * R[0];
                float v5 = A[5] * R[0];
#pragma unroll
                for (int i = 1; i < 6; i++) {
                    float ri = R[i];
                    v0 = fmaf(A[i * 6 + 0], ri, v0);
                    v1 = fmaf(A[i * 6 + 1], ri, v1);
                    v2 = fmaf(A[i * 6 + 2], ri, v2);
                    v3 = fmaf(A[i * 6 + 3], ri, v3);
                    v4 = fmaf(A[i * 6 + 4], ri, v4);
                    v5 = fmaf(A[i * 6 + 5], ri, v5);
                }
                C[0] = cm[0] * frcp(v0);
                C[1] = cm[1] * frcp(v1);
                C[2] = cm[2] * frcp(v2);
                C[3] = cm[3] * frcp(v3);
                C[4] = cm[4] * frcp(v4);
                C[5] = cm[5] * frcp(v5);
            }
            bool conv =
                fabsf(C[0] - C0o) <= 1e-5f * fabsf(C[0]) &&
                fabsf(C[1] - C1o) <= 1e-5f * fabsf(C[1]) &&
                fabsf(C[2] - C2o) <= 1e-5f * fabsf(C[2]) &&
                fabsf(C[3] - C3o) <= 1e-5f * fabsf(C[3]) &&
                fabsf(C[4] - C4o) <= 1e-5f * fabsf(C[4]) &&
                fabsf(C[5] - C5o) <= 1e-5f * fabsf(C[5]);
            if (conv) break;     // per-thread exit: no warp-max tax
        }

        int e = d_idx[s];
        float* o = out + (size_t)e * 49;
#pragma unroll
        for (int i = 0; i < 6; i++) {
            float Ri = R[i];
#pragma unroll
            for (int j = 0; j < 6; j++)
                o[i * 7 + j] = A[i * 6 + j] * Ri * C[j];
        }
    }

    // last-block-out reset of the straggler counter (replaces sk_reset):
    // every block increments d_done at its end; the final block (all reads
    // of d_cnt already done) resets both. Graph-safe, deterministic.
    __syncthreads();
    if (threadIdx.x == 0) {
        int ticket = atomicAdd(&d_done, 1);
        if (ticket == (int)gridDim.x - 1) {
            d_cnt = 0;
            d_done = 0;
        }
    }
}

extern "C" void kernel_launch(void* const* d_in, const int* in_sizes, int n_in,
                              void* d_out, int out_size) {
    const float* margins = (const float*)d_in[0];
    const float* W1   = (const float*)d_in[1];
    const float* b1   = (const float*)d_in[2];
    const float* W2   = (const float*)d_in[3];
    const float* b2   = (const float*)d_in[4];
    const float* W3   = (const float*)d_in[5];
    const float* b3   = (const float*)d_in[6];
    const float* Wtau = (const float*)d_in[7];

    int B = in_sizes[0] / 12;
    int blocks = (B + 255) / 256;
    sk_kernel<<<blocks, 256>>>(margins, W1, b1, W2, b2, W3, b3, Wtau,
                               (float*)d_out, B);
    sk_tail<<<TAILB, 256>>>(Wtau, (float*)d_out, B);
}

// round 17
// speedup vs baseline: 1.1607x; 1.1607x over previous
#include <cuda_runtime.h>

#define ITERS 100

typedef unsigned long long u64;

__device__ __forceinline__ float frcp(float x) {
    float r; asm("rcp.approx.f32 %0,%1;" : "=f"(r) : "f"(x)); return r;
}
__device__ __forceinline__ float squashf(float x) {
    float s = frcp(1.0f + __expf(-x));
    return fmaf(0.96f, s, 0.02f);
}
// packed helpers: used ONLY in the feed-forward prologue, where weight
// pairs load directly from smem as LDS.64 (no marshaling movs).
__device__ __forceinline__ u64 pk2(float a, float b) {
    u64 r; asm("mov.b64 %0,{%1,%2};" : "=l"(r) : "f"(a), "f"(b)); return r;
}
__device__ __forceinline__ void up2(u64 v, float& a, float& b) {
    asm("mov.b64 {%0,%1},%2;" : "=f"(a), "=f"(b) : "l"(v));
}
__device__ __forceinline__ u64 ffma2(u64 a, u64 b, u64 c) {
    u64 r; asm("fma.rn.f32x2 %0,%1,%2,%3;" : "=l"(r) : "l"(a), "l"(b), "l"(c));
    return r;
}

__global__ void __launch_bounds__(256, 3) sk_kernel(
    const float* __restrict__ margins,
    const float* __restrict__ W1, const float* __restrict__ b1,
    const float* __restrict__ W2, const float* __restrict__ b2,
    const float* __restrict__ W3, const float* __restrict__ b3,
    const float* __restrict__ Wtau,
    float* __restrict__ out, int B)
{
    __shared__ __align__(16) float sW1[12 * 32];
    __shared__ __align__(16) float sW2[32 * 16];
    __shared__ __align__(16) float sW3[16 * 18];
    __shared__ __align__(16) float sWt[8 * 36];
    __shared__ __align__(16) float sb1[32];
    __shared__ __align__(16) float sb2[16];
    __shared__ __align__(16) float sb3[18];
    __shared__ __align__(16) float sOut[256 * 49];
    __shared__ __align__(16) float sRM[6][256];
    __shared__ __align__(16) float sCM[6][256];

    const int t = threadIdx.x;
    for (int i = t; i < 384; i += 256) sW1[i] = W1[i];
    for (int i = t; i < 512; i += 256) sW2[i] = W2[i];
    for (int i = t; i < 288; i += 256) sW3[i] = W3[i];
    for (int i = t; i < 288; i += 256) sWt[i] = Wtau[i];
    if (t < 32) sb1[t] = b1[t];
    if (t < 16) sb2[t] = b2[t];
    if (t < 18) sb3[t] = b3[t];
    __syncthreads();

    const int b = blockIdx.x * 256 + t;   // grid exactly covers B

    float m[12];
    {
        const float4* mv = (const float4*)margins + (size_t)b * 3;
        float4 q0 = mv[0], q1 = mv[1], q2 = mv[2];
        m[0] = q0.x; m[1] = q0.y; m[2]  = q0.z; m[3]  = q0.w;
        m[4] = q1.x; m[5] = q1.y; m[6]  = q1.z; m[7]  = q1.w;
        m[8] = q2.x; m[9] = q2.y; m[10] = q2.z; m[11] = q2.w;
    }

    // ---- MLP layer 1 (packed over output pairs): 12 -> 32, relu ----
    float h[32];
    {
        u64 hp[16];
        const u64* bp = (const u64*)sb1;
#pragma unroll
        for (int j = 0; j < 16; j++) hp[j] = bp[j];
#pragma unroll
        for (int k = 0; k < 12; k++) {
            u64 xb = pk2(m[k], m[k]);
            const u64* w = (const u64*)(sW1 + k * 32);   // LDS.64 pairs
#pragma unroll
            for (int j = 0; j < 16; j++) hp[j] = ffma2(w[j], xb, hp[j]);
        }
#pragma unroll
        for (int j = 0; j < 16; j++) {
            float a, c; up2(hp[j], a, c);
            h[2 * j]     = fmaxf(a, 0.0f);
            h[2 * j + 1] = fmaxf(c, 0.0f);
        }
    }

    // ---- MLP layer 2 (packed): 32 -> 16, relu ----
    float g[16];
    {
        u64 gp[8];
        const u64* bp = (const u64*)sb2;
#pragma unroll
        for (int j = 0; j < 8; j++) gp[j] = bp[j];
#pragma unroll
        for (int k = 0; k < 32; k++) {
            u64 xb = pk2(h[k], h[k]);
            const u64* w = (const u64*)(sW2 + k * 16);
#pragma unroll
            for (int j = 0; j < 8; j++) gp[j] = ffma2(w[j], xb, gp[j]);
        }
#pragma unroll
        for (int j = 0; j < 8; j++) {
            float a, c; up2(gp[j], a, c);
            g[2 * j]     = fmaxf(a, 0.0f);
            g[2 * j + 1] = fmaxf(c, 0.0f);
        }
    }

    // ---- MLP layer 3 (packed): 16 -> 18 ----
    float p[18];
    {
        u64 pp[9];
        const u64* bp = (const u64*)sb3;
#pragma unroll
        for (int j = 0; j < 9; j++) pp[j] = bp[j];
#pragma unroll
        for (int k = 0; k < 16; k++) {
            u64 xb = pk2(g[k], g[k]);
            const u64* w = (const u64*)(sW3 + k * 18);
#pragma unroll
            for (int j = 0; j < 9; j++) pp[j] = ffma2(w[j], xb, pp[j]);
        }
#pragma unroll
        for (int j = 0; j < 9; j++) up2(pp[j], p[2 * j], p[2 * j + 1]);
    }

    float* so = sOut + t * 49;

    // ---- marginals + mass balancing (proven R6) ----
    {
        float shm[6], shf[6];
        shm[0] = squashf(p[9]);  shm[1] = squashf(p[10]); shm[2] = 1.0f;
        shm[3] = squashf(p[11]); shm[4] = squashf(p[12]); shm[5] = 1.0f;
        shf[0] = squashf(p[13]); shf[1] = squashf(p[14]); shf[2] = 1.0f;
        shf[3] = squashf(p[15]); shf[4] = squashf(p[16]); shf[5] = 1.0f;
        float rv[6], cv[6];
        float sr = 0.f, sc = 0.f;
#pragma unroll
        for (int i = 0; i < 6; i++) {
            rv[i] = m[i] * shm[i];
            cv[i] = m[6 + i] * shf[i];
            sr += rv[i]; sc += cv[i];
            so[i * 7 + 6] = m[i]     - rv[i];
            so[42 + i]    = m[6 + i] - cv[i];
        }
        float s = __fdividef(sc, sr);
#pragma unroll
        for (int i = 0; i < 6; i++) {
            sRM[i][t] = rv[i] * s;
            sCM[i][t] = cv[i];
        }
        so[48] = 0.0f;
        out[(size_t)B * 49 + b] = __expf(p[17]);
    }

    // ---- A0 = exp(einsum) (packed over output pairs) ----
    float A[36];
    {
        u64 dp[18];
#pragma unroll
        for (int e = 0; e < 18; e++) dp[e] = 0ull;
#pragma unroll
        for (int k = 0; k < 8; k++) {
            u64 xb = pk2(p[k], p[k]);
            const u64* w = (const u64*)(sWt + k * 36);
#pragma unroll
            for (int e = 0; e < 18; e++) dp[e] = ffma2(w[e], xb, dp[e]);
        }
#pragma unroll
        for (int e = 0; e < 18; e++) {
            float a, c; up2(dp[e], a, c);
            A[2 * e]     = __expf(a);
            A[2 * e + 1] = __expf(c);
        }
    }

    // ---- factored, balanced Sinkhorn (scalar, proven R14) ----
    float R[6], C[6];
#pragma unroll
    for (int i = 0; i < 6; i++) { R[i] = 1.0f; C[i] = 1.0f; }

#pragma unroll 1
    for (int ob = 0; ob < (ITERS + 2) / 3; ++ob) {
        float C0o = C[0], C1o = C[1], C2o = C[2],
              C3o = C[3], C4o = C[4], C5o = C[5];
        int base = ob * 3;
#pragma unroll
        for (int s = 0; s < 3; ++s) {
            if (base + s >= ITERS) break;
            float u0 = A[0]  * C[0];
            float u1 = A[6]  * C[0];
            float u2 = A[12] * C[0];
            float u3 = A[18] * C[0];
            float u4 = A[24] * C[0];
            float u5 = A[30] * C[0];
#pragma unroll
            for (int j = 1; j < 6; j++) {
                float cj = C[j];
                u0 = fmaf(A[j],      cj, u0);
                u1 = fmaf(A[6 + j],  cj, u1);
                u2 = fmaf(A[12 + j], cj, u2);
                u3 = fmaf(A[18 + j], cj, u3);
                u4 = fmaf(A[24 + j], cj, u4);
                u5 = fmaf(A[30 + j], cj, u5);
            }
            R[0] = sRM[0][t] * frcp(u0);
            R[1] = sRM[1][t] * frcp(u1);
            R[2] = sRM[2][t] * frcp(u2);
            R[3] = sRM[3][t] * frcp(u3);
            R[4] = sRM[4][t] * frcp(u4);
            R[5] = sRM[5][t] * frcp(u5);

            float v0 = A[0] * R[0];
            float v1 = A[1] * R[0];
            float v2 = A[2] * R[0];
            float v3 = A[3] * R[0];
            float v4 = A[4] * R[0];
            float v5 = A[5] * R[0];
#pragma unroll
            for (int i = 1; i < 6; i++) {
                float ri = R[i];
                v0 = fmaf(A[i * 6 + 0], ri, v0);
                v1 = fmaf(A[i * 6 + 1], ri, v1);
                v2 = fmaf(A[i * 6 + 2], ri, v2);
                v3 = fmaf(A[i * 6 + 3], ri, v3);
                v4 = fmaf(A[i * 6 + 4], ri, v4);
                v5 = fmaf(A[i * 6 + 5], ri, v5);
            }
            C[0] = sCM[0][t] * frcp(v0);
            C[1] = sCM[1][t] * frcp(v1);
            C[2] = sCM[2][t] * frcp(v2);
            C[3] = sCM[3][t] * frcp(v3);
            C[4] = sCM[4][t] * frcp(v4);
            C[5] = sCM[5][t] * frcp(v5);
        }
        bool conv =
            fabsf(C[0] - C0o) <= 1e-5f * fabsf(C[0]) &&
            fabsf(C[1] - C1o) <= 1e-5f * fabsf(C[1]) &&
            fabsf(C[2] - C2o) <= 1e-5f * fabsf(C[2]) &&
            fabsf(C[3] - C3o) <= 1e-5f * fabsf(C[3]) &&
            fabsf(C[4] - C4o) <= 1e-5f * fabsf(C[4]) &&
            fabsf(C[5] - C5o) <= 1e-5f * fabsf(C[5]);
        if (__all_sync(__activemask(), conv)) break;
    }

    // ---- final 6x6 block into staging ----
#pragma unroll
    for (int i = 0; i < 6; i++) {
        float Ri = R[i];
#pragma unroll
        for (int j = 0; j < 6; j++)
            so[i * 7 + j] = A[i * 6 + j] * Ri * C[j];
    }

    // ---- coalesced copy-out ----
    __syncthreads();
    {
        float4* dst = (float4*)(out + (size_t)blockIdx.x * (256 * 49));
        const float4* src = (const float4*)sOut;
#pragma unroll
        for (int idx = t, k = 0; k < 13; ++k, idx += 256) {
            if (idx < 3136) dst[idx] = src[idx];
        }
    }
}

extern "C" void kernel_launch(void* const* d_in, const int* in_sizes, int n_in,
                              void* d_out, int out_size) {
    const float* margins = (const float*)d_in[0];
    const float* W1   = (const float*)d_in[1];
    const float* b1   = (const float*)d_in[2];
    const float* W2   = (const float*)d_in[3];
    const float* b2   = (const float*)d_in[4];
    const float* W3   = (const float*)d_in[5];
    const float* b3   = (const float*)d_in[6];
    const float* Wtau = (const float*)d_in[7];

    int B = in_sizes[0] / 12;
    int blocks = (B + 255) / 256;
    sk_kernel<<<blocks, 256>>>(margins, W1, b1, W2, b2, W3, b3, Wtau,
                               (float*)d_out, B);
}